// round 10
// baseline (speedup 1.0000x reference)
#include <cuda_runtime.h>
#include <cstdint>

#define N_NODES 50000
#define E_EDGES 800000
#define DIM 128
#define NEG_INF_F __int_as_float(0xff800000)

#define SCAN_B 49          // 49 blocks * 1024 = 50176 >= N_NODES+1
#define SCAN_T 1024
#define HIST_PER_T 16      // 49*1024*16 = 802816 >= E_EDGES

// ---------------------------------------------------------------------------
// Static device scratch. Invariant: g_cnt, g_cur, g_blksum, g_done* are zero
// at entry of every kernel_launch call (zero-init at load; each call restores
// them). Graph-replay deterministic.
// ---------------------------------------------------------------------------
__device__ float g_agg[(size_t)N_NODES * DIM];
__device__ float g_h[(size_t)N_NODES * DIM];
__device__ int   g_is64;
__device__ int   g_cnt[N_NODES];
__device__ int   g_row[N_NODES + 1];
__device__ int   g_cur[N_NODES];
__device__ int   g_blksum[SCAN_B];
__device__ int   g_done1;
__device__ int   g_done2;
__device__ int2  g_edge[E_EDGES];

// ---------------------------------------------------------------------------
// Kernel 0: fused histogram + exclusive scan (single launch, 49 blocks).
// ---------------------------------------------------------------------------
__global__ void __launch_bounds__(SCAN_T, 1)
histscan_kernel(const int* __restrict__ ei32) {
    __shared__ int sh[SCAN_T];
    __shared__ int pre[SCAN_B];
    __shared__ int offset;
    __shared__ int any_nonzero;
    __shared__ int bar_ok;

    int t = threadIdx.x;
    int b = blockIdx.x;

    if (t == 0) any_nonzero = 0;
    __syncthreads();
    if (t < 256) {
        int k = t * 3000;
        if (ei32[2 * k + 1] != 0) atomicOr(&any_nonzero, 1);
    }
    __syncthreads();
    int is64 = any_nonzero ? 0 : 1;
    if (b == 0 && t == 0) g_is64 = is64;

    const long long* e64 = (const long long*)ei32;
    #pragma unroll
    for (int i = 0; i < HIST_PER_T; ++i) {
        int e = b * SCAN_T + t + i * (SCAN_B * SCAN_T);
        if (e < E_EDGES) {
            int src, dst;
            if (is64) {
                src = (int)e64[e];
                dst = (int)e64[(size_t)E_EDGES + e];
            } else {
                src = ei32[e];
                dst = ei32[(size_t)E_EDGES + e];
            }
            if ((unsigned)src < N_NODES && (unsigned)dst < N_NODES)
                atomicAdd(&g_cnt[dst], 1);
        }
    }

    __threadfence();
    __syncthreads();
    if (t == 0) {
        atomicAdd(&g_done1, 1);
        while (((volatile int*)&g_done1)[0] < SCAN_B) { }
        bar_ok = 1;
    }
    __syncthreads();
    (void)bar_ok;
    __threadfence();

    int idx = b * SCAN_T + t;
    int c = (idx < N_NODES) ? g_cnt[idx] : 0;
    if (idx < N_NODES) g_cnt[idx] = 0;
    sh[t] = c;
    __syncthreads();
    #pragma unroll
    for (int off = 1; off < SCAN_T; off <<= 1) {
        int v = (t >= off) ? sh[t - off] : 0;
        __syncthreads();
        sh[t] += v;
        __syncthreads();
    }
    int ex = sh[t] - c;
    if (t == SCAN_T - 1)
        ((volatile int*)g_blksum)[b] = sh[t] + 1;

    if (t < SCAN_B) {
        int v;
        do { v = ((volatile int*)g_blksum)[t]; } while (v == 0);
        pre[t] = v - 1;
    }
    __syncthreads();
    if (t == 0) {
        int s = 0;
        for (int i = 0; i < b; ++i) s += pre[i];
        offset = s;
    }
    __syncthreads();

    if (idx <= N_NODES) g_row[idx] = ex + offset;
    if (idx < N_NODES)  g_cur[idx] = 0;

    if (t == 0) {
        int old = atomicAdd(&g_done2, 1);
        if (old == SCAN_B - 1) {
            for (int i = 0; i < SCAN_B; ++i) g_blksum[i] = 0;
            g_done1 = 0;
            g_done2 = 0;
        }
    }
}

// ---------------------------------------------------------------------------
// Kernel 1: bucket edges by dst
// ---------------------------------------------------------------------------
__global__ void fill_kernel(const int* __restrict__ ei32,
                            const float* __restrict__ ew) {
    int e = blockIdx.x * blockDim.x + threadIdx.x;
    if (e >= E_EDGES) return;
    int src, dst;
    if (g_is64) {
        const long long* e64 = (const long long*)ei32;
        src = (int)e64[e];
        dst = (int)e64[(size_t)E_EDGES + e];
    } else {
        src = ei32[e];
        dst = ei32[(size_t)E_EDGES + e];
    }
    if ((unsigned)src >= N_NODES || (unsigned)dst >= N_NODES) return;
    int pos = g_row[dst] + atomicAdd(&g_cur[dst], 1);
    g_edge[pos] = make_int2(src, __float_as_int(ew[e]));
}

// ---------------------------------------------------------------------------
// Kernel 2: aggregate. One warp per dst node.
// ---------------------------------------------------------------------------
__device__ __forceinline__ float4 max4w(float4 a, float4 v, float w) {
    a.x = fmaxf(a.x, v.x * w);
    a.y = fmaxf(a.y, v.y * w);
    a.z = fmaxf(a.z, v.z * w);
    a.w = fmaxf(a.w, v.w * w);
    return a;
}

__global__ void agg_kernel(const float* __restrict__ x) {
    int warp = (blockIdx.x * blockDim.x + threadIdx.x) >> 5;
    if (warp >= N_NODES) return;
    int lane = threadIdx.x & 31;
    int beg = __ldg(&g_row[warp]);
    int end = __ldg(&g_row[warp + 1]);

    float4 acc = make_float4(NEG_INF_F, NEG_INF_F, NEG_INF_F, NEG_INF_F);
    int j = beg;
    for (; j + 8 <= end; j += 8) {
        int2 e[8];
        #pragma unroll
        for (int i = 0; i < 8; ++i) e[i] = __ldg(&g_edge[j + i]);
        float4 v[8];
        #pragma unroll
        for (int i = 0; i < 8; ++i)
            v[i] = __ldg(&((const float4*)(x + (size_t)e[i].x * DIM))[lane]);
        #pragma unroll
        for (int i = 0; i < 8; ++i)
            acc = max4w(acc, v[i], __int_as_float(e[i].y));
    }
    if (j + 4 <= end) {
        int2 e[4];
        #pragma unroll
        for (int i = 0; i < 4; ++i) e[i] = __ldg(&g_edge[j + i]);
        float4 v[4];
        #pragma unroll
        for (int i = 0; i < 4; ++i)
            v[i] = __ldg(&((const float4*)(x + (size_t)e[i].x * DIM))[lane]);
        #pragma unroll
        for (int i = 0; i < 4; ++i)
            acc = max4w(acc, v[i], __int_as_float(e[i].y));
        j += 4;
    }
    for (; j < end; ++j) {
        int2 ep = __ldg(&g_edge[j]);
        float4 v = __ldg(&((const float4*)(x + (size_t)ep.x * DIM))[lane]);
        acc = max4w(acc, v, __int_as_float(ep.y));
    }
    if (beg == end) acc = make_float4(0.f, 0.f, 0.f, 0.f);
    ((float4*)(g_agg + (size_t)warp * DIM))[lane] = acc;
}

// ---------------------------------------------------------------------------
// Packed fp32x2 helpers (sm_103a FFMA2 — PTX-only)
// ---------------------------------------------------------------------------
__device__ __forceinline__ unsigned long long pack2(float v) {
    unsigned long long r;
    asm("mov.b64 %0, {%1, %1};" : "=l"(r) : "f"(v));
    return r;
}
__device__ __forceinline__ void fma2(unsigned long long& d,
                                     unsigned long long a,
                                     unsigned long long b) {
    asm("fma.rn.f32x2 %0, %1, %2, %0;" : "+l"(d) : "l"(a), "l"(b));
}
__device__ __forceinline__ void unpack2(unsigned long long v, float& lo, float& hi) {
    asm("mov.b64 {%0, %1}, %2;" : "=f"(lo), "=f"(hi) : "l"(v));
}

// ---------------------------------------------------------------------------
// GEMM: OUT[m,o] = act( IN[m,:] @ W[o,:]^T + B[o] )
// BM=128 x BN=128, 512 threads = 16 warps in a 4x4 grid of 32x32 warp tiles.
// Lane = (lm 0..7) x (ln 0..3); thread tile 4 rows x 8 cols.
// Per warp per k: B = 32 cols = 128B (2 LDS.128, 1 phase each);
//                 A = 32 rows = 128B (1 phase; xs rows padded LDX=132 to
//                 break 512B bank-quad aliasing). 3 phases/k/warp vs 8
//                 FFMA2-issue slots -> FMA-bound.
// ---------------------------------------------------------------------------
#define LDW 132
#define LDX 132
#define BMG 128
#define GEMM_T 512
#define SMEM_BYTES ((128 * LDW + 128 * LDX) * 4)   // 2 * 67584 = 135168 B

template <bool FUSE_INPUT, bool LEAKY>
__global__ void __launch_bounds__(GEMM_T)
mlp_gemm_kernel(const float* __restrict__ A,
                const float* __restrict__ AGG,
                const float* __restrict__ W,
                const float* __restrict__ B,
                const float* __restrict__ EPS,
                float* __restrict__ OUT) {
    extern __shared__ float sm[];
    float* wT = sm;                   // [k=128][o] stride LDW
    float* xs = sm + 128 * LDW;       // [r=128][k=128] stride LDX

    const int tid  = threadIdx.x;
    const int m0   = blockIdx.x * BMG;
    const int wid  = tid >> 5;        // 0..15
    const int lane = tid & 31;
    const int wm   = wid & 3;         // warp row-block 0..3 (32 rows each)
    const int wn   = wid >> 2;        // warp col-block 0..3 (32 cols each)
    const int lm   = lane >> 2;       // 0..7 -> rows wm*32 + lm*4 .. +3
    const int ln   = lane & 3;        // 0..3 -> cols wn*32 + ln*8 .. +7

    const int row0 = wm * 32 + lm * 4;
    const int col0 = wn * 32 + ln * 8;

    float bias[8];
    #pragma unroll
    for (int j = 0; j < 8; ++j) bias[j] = __ldg(&B[col0 + j]);

    // Stage W transposed: wT[k][o] = W[o*128 + k]
    for (int idx = tid; idx < 128 * 128; idx += GEMM_T) {
        int o = idx >> 7;
        int k = idx & 127;
        wT[k * LDW + o] = W[idx];
    }

    // Stage input tile row-major (optionally fused with agg/eps)
    float scale = 1.0f;
    if (FUSE_INPUT) scale = 1.0f + EPS[0];
    #pragma unroll
    for (int p = 0; p < 8; ++p) {
        int r  = p * 16 + (tid >> 5);  // 0..127
        int c4 = tid & 31;             // float4 feature group
        int m  = m0 + r;
        float4 v = make_float4(0.f, 0.f, 0.f, 0.f);
        if (m < N_NODES) {
            v = ((const float4*)(A + (size_t)m * DIM))[c4];
            if (FUSE_INPUT) {
                float4 g = ((const float4*)(AGG + (size_t)m * DIM))[c4];
                v.x = scale * v.x + g.x;
                v.y = scale * v.y + g.y;
                v.z = scale * v.z + g.z;
                v.w = scale * v.w + g.w;
            }
        }
        *(float4*)(xs + r * LDX + c4 * 4) = v;
    }
    __syncthreads();

    unsigned long long acc[4][4];
    #pragma unroll
    for (int i = 0; i < 4; ++i)
        #pragma unroll
        for (int j = 0; j < 4; ++j) acc[i][j] = 0ull;

    const float* aBase = xs + row0 * LDX;
    const float* bBase = wT + col0;

    #pragma unroll 4
    for (int kc = 0; kc < 32; ++kc) {
        // A: 4 rows x 4 consecutive k each (one LDS.128 per row)
        float4 a[4];
        #pragma unroll
        for (int i = 0; i < 4; ++i)
            a[i] = *(const float4*)(aBase + i * LDX + kc * 4);

        #pragma unroll
        for (int q = 0; q < 4; ++q) {
            int k = kc * 4 + q;
            ulonglong2 bA = *(const ulonglong2*)(bBase + k * LDW);       // cols col0..+3
            ulonglong2 bB = *(const ulonglong2*)(bBase + k * LDW + 4);   // cols col0+4..+7
            const float* af0 = (const float*)&a[0];
            const float* af1 = (const float*)&a[1];
            const float* af2 = (const float*)&a[2];
            const float* af3 = (const float*)&a[3];
            unsigned long long a0 = pack2(af0[q]);
            unsigned long long a1 = pack2(af1[q]);
            unsigned long long a2 = pack2(af2[q]);
            unsigned long long a3 = pack2(af3[q]);
            fma2(acc[0][0], a0, bA.x); fma2(acc[0][1], a0, bA.y);
            fma2(acc[0][2], a0, bB.x); fma2(acc[0][3], a0, bB.y);
            fma2(acc[1][0], a1, bA.x); fma2(acc[1][1], a1, bA.y);
            fma2(acc[1][2], a1, bB.x); fma2(acc[1][3], a1, bB.y);
            fma2(acc[2][0], a2, bA.x); fma2(acc[2][1], a2, bA.y);
            fma2(acc[2][2], a2, bB.x); fma2(acc[2][3], a2, bB.y);
            fma2(acc[3][0], a3, bA.x); fma2(acc[3][1], a3, bA.y);
            fma2(acc[3][2], a3, bB.x); fma2(acc[3][3], a3, bB.y);
        }
    }

    // Epilogue: bias (+LeakyReLU) and store (two float4 per row)
    #pragma unroll
    for (int i = 0; i < 4; ++i) {
        int m = m0 + row0 + i;
        if (m < N_NODES) {
            float o[8];
            unpack2(acc[i][0], o[0], o[1]);
            unpack2(acc[i][1], o[2], o[3]);
            unpack2(acc[i][2], o[4], o[5]);
            unpack2(acc[i][3], o[6], o[7]);
            #pragma unroll
            for (int j = 0; j < 8; ++j) {
                float v = o[j] + bias[j];
                if (LEAKY) v = (v >= 0.0f) ? v : 0.01f * v;
                o[j] = v;
            }
            *(float4*)(OUT + (size_t)m * DIM + col0)     = make_float4(o[0], o[1], o[2], o[3]);
            *(float4*)(OUT + (size_t)m * DIM + col0 + 4) = make_float4(o[4], o[5], o[6], o[7]);
        }
    }
}

// ---------------------------------------------------------------------------
// Launcher — order: histscan(0), fill(1), agg(2), gemm1(3) <- ncu, gemm2(4)
// ---------------------------------------------------------------------------
extern "C" void kernel_launch(void* const* d_in, const int* in_sizes, int n_in,
                              void* d_out, int out_size) {
    const float* x   = (const float*)d_in[0];
    const int*   ei  = (const int*)d_in[1];
    const float* ew  = (const float*)d_in[2];
    const float* w1  = (const float*)d_in[3];
    const float* b1  = (const float*)d_in[4];
    const float* w2  = (const float*)d_in[5];
    const float* b2  = (const float*)d_in[6];
    const float* eps = (const float*)d_in[7];
    float*       out = (float*)d_out;

    cudaFuncSetAttribute(mlp_gemm_kernel<true, true>,
                         cudaFuncAttributeMaxDynamicSharedMemorySize, SMEM_BYTES);
    cudaFuncSetAttribute(mlp_gemm_kernel<false, false>,
                         cudaFuncAttributeMaxDynamicSharedMemorySize, SMEM_BYTES);

    void *agg_p = nullptr, *h_p = nullptr;
    cudaGetSymbolAddress(&agg_p, g_agg);
    cudaGetSymbolAddress(&h_p,   g_h);
    float* agg = (float*)agg_p;
    float* h   = (float*)h_p;

    histscan_kernel<<<SCAN_B, SCAN_T>>>(ei);                         // 0
    fill_kernel<<<(E_EDGES + 255) / 256, 256>>>(ei, ew);             // 1
    agg_kernel<<<(N_NODES * 32 + 255) / 256, 256>>>(x);              // 2

    {
        int blocks = (N_NODES + BMG - 1) / BMG;
        mlp_gemm_kernel<true, true><<<blocks, GEMM_T, SMEM_BYTES>>>(   // 3 <- ncu
            x, agg, w1, b1, eps, h);
        mlp_gemm_kernel<false, false><<<blocks, GEMM_T, SMEM_BYTES>>>( // 4
            h, nullptr, w2, b2, eps, out);
    }
}